// round 13
// baseline (speedup 1.0000x reference)
#include <cuda_runtime.h>
#include <math.h>

// ---------------- device scratch (static, no allocation) ----------------
__device__ float g_xiou[2048 * 2304];   // tree_features @ W_iou^T + b_iou
__device__ float g_xf  [2048 * 768];    // tree_features @ W_f^T + b_f (rows 0..1023 used)
__device__ float g_xih [2048 * 3072];   // features @ W_ih^T + b_ih + b_hh
__device__ float g_h   [2048 * 768];    // tree h
__device__ float g_c   [2048 * 768];    // tree c
__device__ float g_iou [512  * 2304];   // (child-h-sum) @ U_iou^T per level
__device__ float g_fh  [1024 * 768];    // child_h @ U_f^T per level
__device__ float2 g_hbuf2[2 * 768];     // h ring: (value, step tag) pairs, depth 2
__device__ float g_cls [2048 * 1536];   // concat(tree_h, lstm_h) written in place
__device__ float g_logits[2048 * 128];
__device__ unsigned g_arrive;           // lstm CTA residency counter (reset each call)

// ---------------- helpers ----------------
__device__ __forceinline__ unsigned long long pk2(float x, float y) {
    unsigned long long d;
    asm("mov.b64 %0, {%1, %2};" : "=l"(d) : "f"(x), "f"(y));
    return d;
}
__device__ __forceinline__ void upk2(unsigned long long d, float& x, float& y) {
    asm("mov.b64 {%0, %1}, %2;" : "=f"(x), "=f"(y) : "l"(d));
}
__device__ __forceinline__ void fma2(unsigned long long& c, unsigned long long a,
                                     unsigned long long b) {
    asm("fma.rn.f32x2 %0, %1, %2, %0;" : "+l"(c) : "l"(a), "l"(b));
}
__device__ __forceinline__ float4 ldcg4(const float4* p) {
    float4 v;
    asm volatile("ld.global.cg.v4.f32 {%0,%1,%2,%3}, [%4];"
                 : "=f"(v.x), "=f"(v.y), "=f"(v.z), "=f"(v.w) : "l"(p));
    return v;
}
__device__ __forceinline__ void stcg2(float2* p, float v, float tag) {
    asm volatile("st.global.cg.v2.f32 [%0], {%1,%2};" :: "l"(p), "f"(v), "f"(tag));
}
__device__ __forceinline__ unsigned ld_acq(const unsigned* p) {
    unsigned v;
    asm volatile("ld.acquire.gpu.u32 %0, [%1];" : "=r"(v) : "l"(p));
    return v;
}
__device__ __forceinline__ void red_rel(unsigned* p, unsigned v) {
    asm volatile("red.release.gpu.add.u32 [%0], %1;" :: "l"(p), "r"(v));
}
// fast approx activations (lstm only): tanh.approx is a single MUFU op
__device__ __forceinline__ float tanhfast(float x) {
    float y;
    asm("tanh.approx.f32 %0, %1;" : "=f"(y) : "f"(x));
    return y;
}
__device__ __forceinline__ float sigfast(float x) {
    return fmaf(0.5f, tanhfast(0.5f * x), 0.5f);
}
// exact-ish versions (tree path keeps these)
__device__ __forceinline__ float fsig(float x) {
    return __fdividef(1.0f, 1.0f + __expf(-x));
}
__device__ __forceinline__ float ftanh(float x) {
    float xx = fminf(fmaxf(x, -15.0f), 15.0f);
    float e = __expf(2.0f * xx);
    return __fdividef(e - 1.0f, e + 1.0f);
}

// ---------------- 128x64 tile GEMM, M-paired f32x2 FFMA ----------------
struct GemmP {
    const float* A; const float* B; const float* b1; const float* b2;
    float* C; int M, N, K, lda, ldb, hs, addC;
};

__device__ __forceinline__ float4 loadA(const GemmP& p, int r, int koff) {
    if (r >= p.M) return make_float4(0.f, 0.f, 0.f, 0.f);
    if (p.hs >= 0) {
        int c0 = 2 * (p.hs + r) + 1;
        float4 a = *(const float4*)(g_h + (size_t)c0 * 768 + koff);
        if (c0 + 1 < 2048) {
            float4 a2 = *(const float4*)(g_h + (size_t)(c0 + 1) * 768 + koff);
            a.x += a2.x; a.y += a2.y; a.z += a2.z; a.w += a2.w;
        }
        return a;
    }
    return *(const float4*)(p.A + (size_t)r * p.lda + koff);
}

__device__ __forceinline__ void gemm_tile(const GemmP p, int tile) {
    __shared__ __align__(16) float As[16][132];
    __shared__ __align__(16) float Bs[16][68];
    const int ntx = p.N >> 6;
    const int bm = (tile / ntx) * 128;
    const int bn = (tile % ntx) * 64;
    const int tid = threadIdx.x;
    const int ty = tid >> 4;
    const int tx = tid & 15;
    const int ar = tid >> 2;
    const int ac = (tid & 3) * 4;

    unsigned long long acc[4][4];
#pragma unroll
    for (int i = 0; i < 4; i++)
#pragma unroll
        for (int jj = 0; jj < 4; jj++) acc[i][jj] = 0ull;

    const float* Brow = p.B + (size_t)(bn + ar) * p.ldb + ac;

    float4 a0 = loadA(p, bm + ar, ac);
    float4 a1 = loadA(p, bm + ar + 64, ac);
    float4 bv = *(const float4*)(Brow);

    for (int k0 = 0; k0 < p.K; k0 += 16) {
        __syncthreads();
        As[ac + 0][ar] = a0.x; As[ac + 1][ar] = a0.y;
        As[ac + 2][ar] = a0.z; As[ac + 3][ar] = a0.w;
        As[ac + 0][ar + 64] = a1.x; As[ac + 1][ar + 64] = a1.y;
        As[ac + 2][ar + 64] = a1.z; As[ac + 3][ar + 64] = a1.w;
        Bs[ac + 0][ar] = bv.x; Bs[ac + 1][ar] = bv.y;
        Bs[ac + 2][ar] = bv.z; Bs[ac + 3][ar] = bv.w;
        __syncthreads();
        if (k0 + 16 < p.K) {
            a0 = loadA(p, bm + ar, k0 + 16 + ac);
            a1 = loadA(p, bm + ar + 64, k0 + 16 + ac);
            bv = *(const float4*)(Brow + k0 + 16);
        }
#pragma unroll
        for (int kk = 0; kk < 16; kk++) {
            float4 ra0 = *(const float4*)&As[kk][ty * 8];
            float4 ra1 = *(const float4*)&As[kk][ty * 8 + 4];
            float4 rb  = *(const float4*)&Bs[kk][tx * 4];
            unsigned long long ap0 = pk2(ra0.x, ra0.y);
            unsigned long long ap1 = pk2(ra0.z, ra0.w);
            unsigned long long ap2 = pk2(ra1.x, ra1.y);
            unsigned long long ap3 = pk2(ra1.z, ra1.w);
            unsigned long long bb;
            bb = pk2(rb.x, rb.x);
            fma2(acc[0][0], ap0, bb); fma2(acc[1][0], ap1, bb);
            fma2(acc[2][0], ap2, bb); fma2(acc[3][0], ap3, bb);
            bb = pk2(rb.y, rb.y);
            fma2(acc[0][1], ap0, bb); fma2(acc[1][1], ap1, bb);
            fma2(acc[2][1], ap2, bb); fma2(acc[3][1], ap3, bb);
            bb = pk2(rb.z, rb.z);
            fma2(acc[0][2], ap0, bb); fma2(acc[1][2], ap1, bb);
            fma2(acc[2][2], ap2, bb); fma2(acc[3][2], ap3, bb);
            bb = pk2(rb.w, rb.w);
            fma2(acc[0][3], ap0, bb); fma2(acc[1][3], ap1, bb);
            fma2(acc[2][3], ap2, bb); fma2(acc[3][3], ap3, bb);
        }
    }

    const int col = bn + tx * 4;
    float4 bias = make_float4(0.f, 0.f, 0.f, 0.f);
    if (p.b1) {
        float4 bb = *(const float4*)(p.b1 + col);
        bias.x += bb.x; bias.y += bb.y; bias.z += bb.z; bias.w += bb.w;
    }
    if (p.b2) {
        float4 bb = *(const float4*)(p.b2 + col);
        bias.x += bb.x; bias.y += bb.y; bias.z += bb.z; bias.w += bb.w;
    }
#pragma unroll
    for (int m = 0; m < 4; m++) {
        float4 lo, hi;
        upk2(acc[m][0], lo.x, hi.x); upk2(acc[m][1], lo.y, hi.y);
        upk2(acc[m][2], lo.z, hi.z); upk2(acc[m][3], lo.w, hi.w);
        int row0 = bm + ty * 8 + 2 * m;
        if (row0 < p.M) {
            float* cp = p.C + (size_t)row0 * p.N + col;
            float4 o = make_float4(lo.x + bias.x, lo.y + bias.y, lo.z + bias.z, lo.w + bias.w);
            if (p.addC) {
                float4 c = *(const float4*)cp;
                o.x += c.x; o.y += c.y; o.z += c.z; o.w += c.w;
            }
            *(float4*)cp = o;
        }
        if (row0 + 1 < p.M) {
            float* cp = p.C + (size_t)(row0 + 1) * p.N + col;
            float4 o = make_float4(hi.x + bias.x, hi.y + bias.y, hi.z + bias.z, hi.w + bias.w);
            if (p.addC) {
                float4 c = *(const float4*)cp;
                o.x += c.x; o.y += c.y; o.z += c.z; o.w += c.w;
            }
            *(float4*)cp = o;
        }
    }
}

__global__ void __launch_bounds__(256) gemm_single(GemmP p) {
    gemm_tile(p, blockIdx.x);
}

__global__ void __launch_bounds__(256) gemm_dual(GemmP p1, GemmP p2, int t1) {
    int b = blockIdx.x;
    GemmP p = (b < t1) ? p1 : p2;
    int tile = (b < t1) ? b : b - t1;
    gemm_tile(p, tile);
}

// ---------------- tree LSTM elementwise kernels ----------------
__global__ void leaf_combine() {
    int idx = blockIdx.x * blockDim.x + threadIdx.x;   // 1024*768 exact
    int p = 1024 + idx / 768, jj = idx % 768;
    const float* xr = g_xiou + (size_t)p * 2304;
    float i = fsig(xr[jj]);
    float o = fsig(xr[768 + jj]);
    float u = ftanh(xr[1536 + jj]);
    float cn = i * u;
    float hn = o * ftanh(cn);
    g_c[(size_t)p * 768 + jj] = cn;
    g_h[(size_t)p * 768 + jj] = hn;
    g_cls[(size_t)p * 1536 + jj] = hn;
}

__global__ void node_combine(int s, int cnt, int cs) {
    int idx = blockIdx.x * blockDim.x + threadIdx.x;
    if (idx >= cnt * 768) return;
    int r = idx / 768, jj = idx % 768, p = s + r;
    const float* xr = g_xiou + (size_t)p * 2304;
    const float* ir = g_iou + (size_t)r * 2304;
    float i = fsig(xr[jj] + ir[jj]);
    float o = fsig(xr[768 + jj] + ir[768 + jj]);
    float u = ftanh(xr[1536 + jj] + ir[1536 + jj]);
    float xfv = g_xf[(size_t)p * 768 + jj];
    int c0 = 2 * p + 1, c1 = 2 * p + 2;
    float fc = fsig(xfv + g_fh[(size_t)(c0 - cs) * 768 + jj]) * g_c[(size_t)c0 * 768 + jj];
    if (c1 < 2048)
        fc += fsig(xfv + g_fh[(size_t)(c1 - cs) * 768 + jj]) * g_c[(size_t)c1 * 768 + jj];
    float cn = i * u + fc;
    float hn = o * ftanh(cn);
    g_c[(size_t)p * 768 + jj] = cn;
    g_h[(size_t)p * 768 + jj] = hn;
    g_cls[(size_t)p * 1536 + jj] = hn;
}

// ---------------- sequential LSTM: persistent, W_hh in registers ----------
// 96 CTAs x 256 threads (R8 layout). Warp w of CTA b owns output j = b*8+w.
// Tagged depth-2 ring; smem staging + 1 barrier/step.
// R13 chain cuts: ring-of-3 pipelined polling (samples the line every ~85cyc
// instead of ~300) and single-MUFU tanh.approx activations. NO nanosleep
// (twice confirmed harmful).
__global__ void __launch_bounds__(256) lstm_seq(const float* __restrict__ Whh) {
    __shared__ __align__(16) float hsm[2][768];
    const int tid = threadIdx.x;
    const int w = tid >> 5, l = tid & 31;
    const int j = blockIdx.x * 8 + w;

    if (tid == 0) red_rel(&g_arrive, 1u);   // residency signal

    unsigned long long wr2[4][12];
#pragma unroll
    for (int g = 0; g < 4; g++) {
        const float* base = Whh + (size_t)(g * 768 + j) * 768;
#pragma unroll
        for (int i = 0; i < 6; i++) {
            float4 v = *(const float4*)(base + 128 * i + l * 4);
            wr2[g][2 * i]     = pk2(v.x, v.y);
            wr2[g][2 * i + 1] = pk2(v.z, v.w);
        }
    }

    float cprev = 0.0f;
    for (int t = 0; t < 2048; t++) {
        const int par = t & 1;
        // x gates are h-independent: issue before the poll
        const float* xb = g_xih + (size_t)t * 3072 + j;
        float xi = xb[0], xf_ = xb[768], xg = xb[1536], xo = xb[2304];

        if (tid < 192) {
            const float4* base = (const float4*)(g_hbuf2 + par * 768);
            const float4* pa = base + tid;
            const float4* pb = base + 192 + tid;
            // ring-of-3 pipelined sampling: 3 in-flight loads per target, so
            // the line is sampled ~every (round-trip/3) instead of per round.
            float4 qa0 = ldcg4(pa), qb0 = ldcg4(pb);
            float4 qa1 = ldcg4(pa), qb1 = ldcg4(pb);
            float4 qa2 = ldcg4(pa), qb2 = ldcg4(pb);
            float4 va, vb;
            for (;;) {
                if (__float_as_int(qa0.y) == t && __float_as_int(qa0.w) == t &&
                    __float_as_int(qb0.y) == t && __float_as_int(qb0.w) == t) {
                    va = qa0; vb = qb0; break;
                }
                qa0 = ldcg4(pa); qb0 = ldcg4(pb);
                if (__float_as_int(qa1.y) == t && __float_as_int(qa1.w) == t &&
                    __float_as_int(qb1.y) == t && __float_as_int(qb1.w) == t) {
                    va = qa1; vb = qb1; break;
                }
                qa1 = ldcg4(pa); qb1 = ldcg4(pb);
                if (__float_as_int(qa2.y) == t && __float_as_int(qa2.w) == t &&
                    __float_as_int(qb2.y) == t && __float_as_int(qb2.w) == t) {
                    va = qa2; vb = qb2; break;
                }
                qa2 = ldcg4(pa); qb2 = ldcg4(pb);
            }
            hsm[par][2 * tid]             = va.x;
            hsm[par][2 * tid + 1]         = va.z;
            hsm[par][2 * (192 + tid)]     = vb.x;
            hsm[par][2 * (192 + tid) + 1] = vb.z;
        }
        __syncthreads();                        // h(t) staged in smem

        unsigned long long A0 = 0ull, A1 = 0ull, A2 = 0ull, A3 = 0ull;
#pragma unroll
        for (int i = 0; i < 6; i++) {
            float4 hv = *((const float4*)hsm[par] + i * 32 + l);
            unsigned long long h01 = pk2(hv.x, hv.y);
            unsigned long long h23 = pk2(hv.z, hv.w);
            fma2(A0, wr2[0][2 * i], h01); fma2(A0, wr2[0][2 * i + 1], h23);
            fma2(A1, wr2[1][2 * i], h01); fma2(A1, wr2[1][2 * i + 1], h23);
            fma2(A2, wr2[2][2 * i], h01); fma2(A2, wr2[2][2 * i + 1], h23);
            fma2(A3, wr2[3][2 * i], h01); fma2(A3, wr2[3][2 * i + 1], h23);
        }
        float a0, a1, a2, a3, tlo, thi;
        upk2(A0, tlo, thi); a0 = tlo + thi;
        upk2(A1, tlo, thi); a1 = tlo + thi;
        upk2(A2, tlo, thi); a2 = tlo + thi;
        upk2(A3, tlo, thi); a3 = tlo + thi;
#pragma unroll
        for (int off = 16; off > 0; off >>= 1) {
            a0 += __shfl_xor_sync(0xffffffffu, a0, off);
            a1 += __shfl_xor_sync(0xffffffffu, a1, off);
            a2 += __shfl_xor_sync(0xffffffffu, a2, off);
            a3 += __shfl_xor_sync(0xffffffffu, a3, off);
        }
        if (l == 0) {
            float iv = sigfast(a0 + xi);
            float fv = sigfast(a1 + xf_);
            float gv = tanhfast(a2 + xg);
            float ov = sigfast(a3 + xo);
            float cn = fv * cprev + iv * gv;
            cprev = cn;
            float hn = ov * tanhfast(cn);
            stcg2(&g_hbuf2[((t + 1) & 1) * 768 + j], hn, __int_as_float(t + 1));
            __stcg(&g_cls[(size_t)t * 1536 + 768 + j], hn);
        }
        // no bottom barrier: hsm double-buffered; tag ring is 2-deep safe
    }
}

// ---------------- residency gate ----------------
__global__ void wait_resident(unsigned target) {
    if (threadIdx.x == 0) {
        while (ld_acq(&g_arrive) < target) {}
    }
}

// ---------------- misc ----------------
__global__ void zero_misc() {
    int i = blockIdx.x * blockDim.x + threadIdx.x;  // 384 float4 = 2*768 float2
    if (i < 384) ((float4*)g_hbuf2)[i] = make_float4(0.f, 0.f, 0.f, 0.f);
    if (i == 0) g_arrive = 0u;
}

__global__ void logsoftmax_col(float* __restrict__ out) {
    int o = blockIdx.x;
    int tid = threadIdx.x;
    __shared__ float red[256];
    float m = -1e30f;
    for (int t = tid; t < 2048; t += 256) m = fmaxf(m, g_logits[(size_t)t * 128 + o]);
    red[tid] = m; __syncthreads();
    for (int st = 128; st > 0; st >>= 1) {
        if (tid < st) red[tid] = fmaxf(red[tid], red[tid + st]);
        __syncthreads();
    }
    m = red[0]; __syncthreads();
    float s = 0.0f;
    for (int t = tid; t < 2048; t += 256) s += expf(g_logits[(size_t)t * 128 + o] - m);
    red[tid] = s; __syncthreads();
    for (int st = 128; st > 0; st >>= 1) {
        if (tid < st) red[tid] += red[tid + st];
        __syncthreads();
    }
    float lse = m + logf(red[0]);
    for (int t = tid; t < 2048; t += 256)
        out[(size_t)t * 128 + o] = g_logits[(size_t)t * 128 + o] - lse;
}

// ---------------- host ----------------
static inline int ntiles(int M, int N) { return ((M + 127) / 128) * (N / 64); }

extern "C" void kernel_launch(void* const* d_in, const int* in_sizes, int n_in,
                              void* d_out, int out_size)
{
    const float* tree_features = (const float*)d_in[0];
    const float* features      = (const float*)d_in[1];
    const float* W_iou = (const float*)d_in[2];
    const float* b_iou = (const float*)d_in[3];
    const float* U_iou = (const float*)d_in[4];
    const float* W_f   = (const float*)d_in[5];
    const float* b_f   = (const float*)d_in[6];
    const float* U_f   = (const float*)d_in[7];
    const float* W_ih  = (const float*)d_in[8];
    const float* b_ih  = (const float*)d_in[9];
    const float* W_hh  = (const float*)d_in[10];
    const float* b_hh  = (const float*)d_in[11];
    const float* W_cls = (const float*)d_in[12];
    const float* b_cls = (const float*)d_in[13];
    float* out = (float*)d_out;

    float *xiou, *xf, *xih, *h, *iou, *fh, *cls, *logits;
    cudaGetSymbolAddress((void**)&xiou,   g_xiou);
    cudaGetSymbolAddress((void**)&xf,     g_xf);
    cudaGetSymbolAddress((void**)&xih,    g_xih);
    cudaGetSymbolAddress((void**)&h,      g_h);
    cudaGetSymbolAddress((void**)&iou,    g_iou);
    cudaGetSymbolAddress((void**)&fh,     g_fh);
    cudaGetSymbolAddress((void**)&cls,    g_cls);
    cudaGetSymbolAddress((void**)&logits, g_logits);

    static cudaStream_t s2 = nullptr;
    static cudaEvent_t evFork = nullptr, evJoin = nullptr;
    if (!s2) {
        cudaStreamCreateWithFlags(&s2, cudaStreamNonBlocking);
        cudaEventCreateWithFlags(&evFork, cudaEventDisableTiming);
        cudaEventCreateWithFlags(&evJoin, cudaEventDisableTiming);
    }

    // ---- reset ring + residency counter + full xih GEMM (stream 0) ----
    zero_misc<<<3, 256>>>();
    GemmP pih = { features, W_ih, b_ih, b_hh, xih, 2048, 3072, 768, 768, 768, -1, 0 };
    gemm_single<<<ntiles(2048, 3072), 256>>>(pih);

    // ---- fork: seq LSTM on its own stream ----
    cudaEventRecord(evFork, 0);
    cudaStreamWaitEvent(s2, evFork, 0);
    lstm_seq<<<96, 256, 0, s2>>>(W_hh);
    cudaEventRecord(evJoin, s2);

    // ---- gate stream 0 until all 96 LSTM CTAs are resident ----
    wait_resident<<<1, 32>>>(96u);

    // ---- tree branch (stream 0, overlapped with LSTM) ----
    GemmP piou = { tree_features, W_iou, b_iou, nullptr, xiou, 2048, 2304, 768, 768, 768, -1, 0 };
    gemm_single<<<ntiles(2048, 2304), 256>>>(piou);
    // x_f only needed for parent nodes 0..1023
    GemmP pxf = { tree_features, W_f, b_f, nullptr, xf, 1024, 768, 768, 768, 768, -1, 0 };
    gemm_single<<<ntiles(1024, 768), 256>>>(pxf);

    leaf_combine<<<(1024 * 768) / 256, 256>>>();
    for (int lvl = 1; lvl <= 11; lvl++) {
        int s, cnt, cs, e;
        if (lvl <= 10) {
            s = 1 << (10 - lvl);
            cnt = s;
            cs = 2 * s + 1;
            int last = 4 * s; if (last > 2047) last = 2047;
            e = last - 2 * s;
        } else {
            s = 0; cnt = 1; cs = 1; e = 2;
        }
        GemmP p1 = { nullptr, U_iou, nullptr, nullptr, iou, cnt, 2304, 768, 768, 768, s, 0 };
        GemmP p2 = { h + (size_t)cs * 768, U_f, nullptr, nullptr, fh, e, 768, 768, 768, 768, -1, 0 };
        int t1 = ntiles(cnt, 2304), t2 = ntiles(e, 768);
        gemm_dual<<<t1 + t2, 256>>>(p1, p2, t1);
        node_combine<<<(cnt * 768 + 255) / 256, 256>>>(s, cnt, cs);
    }

    // ---- classifier tree-half (hidden under LSTM) ----
    GemmP pcls1 = { cls, W_cls, b_cls, nullptr, logits, 2048, 128, 768, 1536, 1536, -1, 0 };
    gemm_single<<<ntiles(2048, 128), 256>>>(pcls1);

    // ---- join + classifier lstm-half (accumulating) + log_softmax over axis 0
    cudaStreamWaitEvent(0, evJoin, 0);
    GemmP pcls2 = { cls + 768, W_cls + 768, nullptr, nullptr, logits, 2048, 128, 768, 1536, 1536, -1, 1 };
    gemm_single<<<ntiles(2048, 128), 256>>>(pcls2);
    logsoftmax_col<<<128, 256>>>(out);
}

// round 14
// speedup vs baseline: 1.8327x; 1.8327x over previous
#include <cuda_runtime.h>
#include <math.h>

// ---------------- device scratch (static, no allocation) ----------------
__device__ float g_xiou[2048 * 2304];   // tree_features @ W_iou^T + b_iou
__device__ float g_xf  [2048 * 768];    // tree_features @ W_f^T + b_f (rows 0..1023 used)
__device__ float g_xih [2048 * 3072];   // features @ W_ih^T + b_ih + b_hh
__device__ float g_h   [2048 * 768];    // tree h
__device__ float g_c   [2048 * 768];    // tree c
__device__ float g_iou [512  * 2304];   // (child-h-sum) @ U_iou^T per level
__device__ float g_fh  [1024 * 768];    // child_h @ U_f^T per level
__device__ float2 g_hbuf2[2 * 768];     // h ring: (value, step tag) pairs, depth 2
__device__ float g_cls [2048 * 1536];   // concat(tree_h, lstm_h) written in place
__device__ float g_logits[2048 * 128];
__device__ unsigned g_arrive;           // lstm CTA residency counter (reset each call)

// ---------------- helpers ----------------
__device__ __forceinline__ unsigned long long pk2(float x, float y) {
    unsigned long long d;
    asm("mov.b64 %0, {%1, %2};" : "=l"(d) : "f"(x), "f"(y));
    return d;
}
__device__ __forceinline__ void upk2(unsigned long long d, float& x, float& y) {
    asm("mov.b64 {%0, %1}, %2;" : "=f"(x), "=f"(y) : "l"(d));
}
__device__ __forceinline__ void fma2(unsigned long long& c, unsigned long long a,
                                     unsigned long long b) {
    asm("fma.rn.f32x2 %0, %1, %2, %0;" : "+l"(c) : "l"(a), "l"(b));
}
__device__ __forceinline__ float4 ldcg4(const float4* p) {
    float4 v;
    asm volatile("ld.global.cg.v4.f32 {%0,%1,%2,%3}, [%4];"
                 : "=f"(v.x), "=f"(v.y), "=f"(v.z), "=f"(v.w) : "l"(p));
    return v;
}
__device__ __forceinline__ void stcg2(float2* p, float v, float tag) {
    asm volatile("st.global.cg.v2.f32 [%0], {%1,%2};" :: "l"(p), "f"(v), "f"(tag));
}
__device__ __forceinline__ unsigned ld_acq(const unsigned* p) {
    unsigned v;
    asm volatile("ld.acquire.gpu.u32 %0, [%1];" : "=r"(v) : "l"(p));
    return v;
}
__device__ __forceinline__ void red_rel(unsigned* p, unsigned v) {
    asm volatile("red.release.gpu.add.u32 [%0], %1;" :: "l"(p), "r"(v));
}
// fast approx activations (lstm only): tanh.approx is a single MUFU op
__device__ __forceinline__ float tanhfast(float x) {
    float y;
    asm("tanh.approx.f32 %0, %1;" : "=f"(y) : "f"(x));
    return y;
}
__device__ __forceinline__ float sigfast(float x) {
    return fmaf(0.5f, tanhfast(0.5f * x), 0.5f);
}
// exact-ish versions (tree path keeps these)
__device__ __forceinline__ float fsig(float x) {
    return __fdividef(1.0f, 1.0f + __expf(-x));
}
__device__ __forceinline__ float ftanh(float x) {
    float xx = fminf(fmaxf(x, -15.0f), 15.0f);
    float e = __expf(2.0f * xx);
    return __fdividef(e - 1.0f, e + 1.0f);
}

// ---------------- 128x64 tile GEMM, M-paired f32x2 FFMA ----------------
struct GemmP {
    const float* A; const float* B; const float* b1; const float* b2;
    float* C; int M, N, K, lda, ldb, hs, addC;
};

__device__ __forceinline__ float4 loadA(const GemmP& p, int r, int koff) {
    if (r >= p.M) return make_float4(0.f, 0.f, 0.f, 0.f);
    if (p.hs >= 0) {
        int c0 = 2 * (p.hs + r) + 1;
        float4 a = *(const float4*)(g_h + (size_t)c0 * 768 + koff);
        if (c0 + 1 < 2048) {
            float4 a2 = *(const float4*)(g_h + (size_t)(c0 + 1) * 768 + koff);
            a.x += a2.x; a.y += a2.y; a.z += a2.z; a.w += a2.w;
        }
        return a;
    }
    return *(const float4*)(p.A + (size_t)r * p.lda + koff);
}

__device__ __forceinline__ void gemm_tile(const GemmP p, int tile) {
    __shared__ __align__(16) float As[16][132];
    __shared__ __align__(16) float Bs[16][68];
    const int ntx = p.N >> 6;
    const int bm = (tile / ntx) * 128;
    const int bn = (tile % ntx) * 64;
    const int tid = threadIdx.x;
    const int ty = tid >> 4;
    const int tx = tid & 15;
    const int ar = tid >> 2;
    const int ac = (tid & 3) * 4;

    unsigned long long acc[4][4];
#pragma unroll
    for (int i = 0; i < 4; i++)
#pragma unroll
        for (int jj = 0; jj < 4; jj++) acc[i][jj] = 0ull;

    const float* Brow = p.B + (size_t)(bn + ar) * p.ldb + ac;

    float4 a0 = loadA(p, bm + ar, ac);
    float4 a1 = loadA(p, bm + ar + 64, ac);
    float4 bv = *(const float4*)(Brow);

    for (int k0 = 0; k0 < p.K; k0 += 16) {
        __syncthreads();
        As[ac + 0][ar] = a0.x; As[ac + 1][ar] = a0.y;
        As[ac + 2][ar] = a0.z; As[ac + 3][ar] = a0.w;
        As[ac + 0][ar + 64] = a1.x; As[ac + 1][ar + 64] = a1.y;
        As[ac + 2][ar + 64] = a1.z; As[ac + 3][ar + 64] = a1.w;
        Bs[ac + 0][ar] = bv.x; Bs[ac + 1][ar] = bv.y;
        Bs[ac + 2][ar] = bv.z; Bs[ac + 3][ar] = bv.w;
        __syncthreads();
        if (k0 + 16 < p.K) {
            a0 = loadA(p, bm + ar, k0 + 16 + ac);
            a1 = loadA(p, bm + ar + 64, k0 + 16 + ac);
            bv = *(const float4*)(Brow + k0 + 16);
        }
#pragma unroll
        for (int kk = 0; kk < 16; kk++) {
            float4 ra0 = *(const float4*)&As[kk][ty * 8];
            float4 ra1 = *(const float4*)&As[kk][ty * 8 + 4];
            float4 rb  = *(const float4*)&Bs[kk][tx * 4];
            unsigned long long ap0 = pk2(ra0.x, ra0.y);
            unsigned long long ap1 = pk2(ra0.z, ra0.w);
            unsigned long long ap2 = pk2(ra1.x, ra1.y);
            unsigned long long ap3 = pk2(ra1.z, ra1.w);
            unsigned long long bb;
            bb = pk2(rb.x, rb.x);
            fma2(acc[0][0], ap0, bb); fma2(acc[1][0], ap1, bb);
            fma2(acc[2][0], ap2, bb); fma2(acc[3][0], ap3, bb);
            bb = pk2(rb.y, rb.y);
            fma2(acc[0][1], ap0, bb); fma2(acc[1][1], ap1, bb);
            fma2(acc[2][1], ap2, bb); fma2(acc[3][1], ap3, bb);
            bb = pk2(rb.z, rb.z);
            fma2(acc[0][2], ap0, bb); fma2(acc[1][2], ap1, bb);
            fma2(acc[2][2], ap2, bb); fma2(acc[3][2], ap3, bb);
            bb = pk2(rb.w, rb.w);
            fma2(acc[0][3], ap0, bb); fma2(acc[1][3], ap1, bb);
            fma2(acc[2][3], ap2, bb); fma2(acc[3][3], ap3, bb);
        }
    }

    const int col = bn + tx * 4;
    float4 bias = make_float4(0.f, 0.f, 0.f, 0.f);
    if (p.b1) {
        float4 bb = *(const float4*)(p.b1 + col);
        bias.x += bb.x; bias.y += bb.y; bias.z += bb.z; bias.w += bb.w;
    }
    if (p.b2) {
        float4 bb = *(const float4*)(p.b2 + col);
        bias.x += bb.x; bias.y += bb.y; bias.z += bb.z; bias.w += bb.w;
    }
#pragma unroll
    for (int m = 0; m < 4; m++) {
        float4 lo, hi;
        upk2(acc[m][0], lo.x, hi.x); upk2(acc[m][1], lo.y, hi.y);
        upk2(acc[m][2], lo.z, hi.z); upk2(acc[m][3], lo.w, hi.w);
        int row0 = bm + ty * 8 + 2 * m;
        if (row0 < p.M) {
            float* cp = p.C + (size_t)row0 * p.N + col;
            float4 o = make_float4(lo.x + bias.x, lo.y + bias.y, lo.z + bias.z, lo.w + bias.w);
            if (p.addC) {
                float4 c = *(const float4*)cp;
                o.x += c.x; o.y += c.y; o.z += c.z; o.w += c.w;
            }
            *(float4*)cp = o;
        }
        if (row0 + 1 < p.M) {
            float* cp = p.C + (size_t)(row0 + 1) * p.N + col;
            float4 o = make_float4(hi.x + bias.x, hi.y + bias.y, hi.z + bias.z, hi.w + bias.w);
            if (p.addC) {
                float4 c = *(const float4*)cp;
                o.x += c.x; o.y += c.y; o.z += c.z; o.w += c.w;
            }
            *(float4*)cp = o;
        }
    }
}

__global__ void __launch_bounds__(256) gemm_single(GemmP p) {
    gemm_tile(p, blockIdx.x);
}

__global__ void __launch_bounds__(256) gemm_dual(GemmP p1, GemmP p2, int t1) {
    int b = blockIdx.x;
    GemmP p = (b < t1) ? p1 : p2;
    int tile = (b < t1) ? b : b - t1;
    gemm_tile(p, tile);
}

// ---------------- tree LSTM elementwise kernels ----------------
__global__ void leaf_combine() {
    int idx = blockIdx.x * blockDim.x + threadIdx.x;   // 1024*768 exact
    int p = 1024 + idx / 768, jj = idx % 768;
    const float* xr = g_xiou + (size_t)p * 2304;
    float i = fsig(xr[jj]);
    float o = fsig(xr[768 + jj]);
    float u = ftanh(xr[1536 + jj]);
    float cn = i * u;
    float hn = o * ftanh(cn);
    g_c[(size_t)p * 768 + jj] = cn;
    g_h[(size_t)p * 768 + jj] = hn;
    g_cls[(size_t)p * 1536 + jj] = hn;
}

__global__ void node_combine(int s, int cnt, int cs) {
    int idx = blockIdx.x * blockDim.x + threadIdx.x;
    if (idx >= cnt * 768) return;
    int r = idx / 768, jj = idx % 768, p = s + r;
    const float* xr = g_xiou + (size_t)p * 2304;
    const float* ir = g_iou + (size_t)r * 2304;
    float i = fsig(xr[jj] + ir[jj]);
    float o = fsig(xr[768 + jj] + ir[768 + jj]);
    float u = ftanh(xr[1536 + jj] + ir[1536 + jj]);
    float xfv = g_xf[(size_t)p * 768 + jj];
    int c0 = 2 * p + 1, c1 = 2 * p + 2;
    float fc = fsig(xfv + g_fh[(size_t)(c0 - cs) * 768 + jj]) * g_c[(size_t)c0 * 768 + jj];
    if (c1 < 2048)
        fc += fsig(xfv + g_fh[(size_t)(c1 - cs) * 768 + jj]) * g_c[(size_t)c1 * 768 + jj];
    float cn = i * u + fc;
    float hn = o * ftanh(cn);
    g_c[(size_t)p * 768 + jj] = cn;
    g_h[(size_t)p * 768 + jj] = hn;
    g_cls[(size_t)p * 1536 + jj] = hn;
}

// ---------------- sequential LSTM: persistent, W_hh in registers ----------
// 96 CTAs x 256 threads (R8 layout, proven best). Warp w of CTA b owns output
// j = b*8+w. Tagged depth-2 ring; smem staging + 1 barrier/step; single
// pending-load polling (the traffic/latency sweet spot per R11/R13).
// Only change vs R8: single-MUFU tanh.approx activations on the writer chain.
__global__ void __launch_bounds__(256) lstm_seq(const float* __restrict__ Whh) {
    __shared__ __align__(16) float hsm[2][768];
    const int tid = threadIdx.x;
    const int w = tid >> 5, l = tid & 31;
    const int j = blockIdx.x * 8 + w;

    if (tid == 0) red_rel(&g_arrive, 1u);   // residency signal

    unsigned long long wr2[4][12];
#pragma unroll
    for (int g = 0; g < 4; g++) {
        const float* base = Whh + (size_t)(g * 768 + j) * 768;
#pragma unroll
        for (int i = 0; i < 6; i++) {
            float4 v = *(const float4*)(base + 128 * i + l * 4);
            wr2[g][2 * i]     = pk2(v.x, v.y);
            wr2[g][2 * i + 1] = pk2(v.z, v.w);
        }
    }

    float cprev = 0.0f;
    for (int t = 0; t < 2048; t++) {
        const int par = t & 1;
        // x gates are h-independent: issue before the poll
        const float* xb = g_xih + (size_t)t * 3072 + j;
        float xi = xb[0], xf_ = xb[768], xg = xb[1536], xo = xb[2304];

        if (tid < 192) {
            const float4* base = (const float4*)(g_hbuf2 + par * 768);
            const float4* pa = base + tid;
            const float4* pb = base + 192 + tid;
            float4 va, vb;
            bool ra = false, rb = false;
            do {
                if (!ra) {
                    va = ldcg4(pa);
                    ra = (__float_as_int(va.y) == t) && (__float_as_int(va.w) == t);
                }
                if (!rb) {
                    vb = ldcg4(pb);
                    rb = (__float_as_int(vb.y) == t) && (__float_as_int(vb.w) == t);
                }
            } while (!(ra && rb));
            hsm[par][2 * tid]             = va.x;
            hsm[par][2 * tid + 1]         = va.z;
            hsm[par][2 * (192 + tid)]     = vb.x;
            hsm[par][2 * (192 + tid) + 1] = vb.z;
        }
        __syncthreads();                        // h(t) staged in smem

        unsigned long long A0 = 0ull, A1 = 0ull, A2 = 0ull, A3 = 0ull;
#pragma unroll
        for (int i = 0; i < 6; i++) {
            float4 hv = *((const float4*)hsm[par] + i * 32 + l);
            unsigned long long h01 = pk2(hv.x, hv.y);
            unsigned long long h23 = pk2(hv.z, hv.w);
            fma2(A0, wr2[0][2 * i], h01); fma2(A0, wr2[0][2 * i + 1], h23);
            fma2(A1, wr2[1][2 * i], h01); fma2(A1, wr2[1][2 * i + 1], h23);
            fma2(A2, wr2[2][2 * i], h01); fma2(A2, wr2[2][2 * i + 1], h23);
            fma2(A3, wr2[3][2 * i], h01); fma2(A3, wr2[3][2 * i + 1], h23);
        }
        float a0, a1, a2, a3, tlo, thi;
        upk2(A0, tlo, thi); a0 = tlo + thi;
        upk2(A1, tlo, thi); a1 = tlo + thi;
        upk2(A2, tlo, thi); a2 = tlo + thi;
        upk2(A3, tlo, thi); a3 = tlo + thi;
#pragma unroll
        for (int off = 16; off > 0; off >>= 1) {
            a0 += __shfl_xor_sync(0xffffffffu, a0, off);
            a1 += __shfl_xor_sync(0xffffffffu, a1, off);
            a2 += __shfl_xor_sync(0xffffffffu, a2, off);
            a3 += __shfl_xor_sync(0xffffffffu, a3, off);
        }
        if (l == 0) {
            float iv = sigfast(a0 + xi);
            float fv = sigfast(a1 + xf_);
            float gv = tanhfast(a2 + xg);
            float ov = sigfast(a3 + xo);
            float cn = fv * cprev + iv * gv;
            cprev = cn;
            float hn = ov * tanhfast(cn);
            stcg2(&g_hbuf2[((t + 1) & 1) * 768 + j], hn, __int_as_float(t + 1));
            __stcg(&g_cls[(size_t)t * 1536 + 768 + j], hn);
        }
        // no bottom barrier: hsm double-buffered; tag ring is 2-deep safe
    }
}

// ---------------- residency gate ----------------
__global__ void wait_resident(unsigned target) {
    if (threadIdx.x == 0) {
        while (ld_acq(&g_arrive) < target) {}
    }
}

// ---------------- misc ----------------
__global__ void zero_misc() {
    int i = blockIdx.x * blockDim.x + threadIdx.x;  // 384 float4 = 2*768 float2
    if (i < 384) ((float4*)g_hbuf2)[i] = make_float4(0.f, 0.f, 0.f, 0.f);
    if (i == 0) g_arrive = 0u;
}

__global__ void logsoftmax_col(float* __restrict__ out) {
    int o = blockIdx.x;
    int tid = threadIdx.x;
    __shared__ float red[256];
    float m = -1e30f;
    for (int t = tid; t < 2048; t += 256) m = fmaxf(m, g_logits[(size_t)t * 128 + o]);
    red[tid] = m; __syncthreads();
    for (int st = 128; st > 0; st >>= 1) {
        if (tid < st) red[tid] = fmaxf(red[tid], red[tid + st]);
        __syncthreads();
    }
    m = red[0]; __syncthreads();
    float s = 0.0f;
    for (int t = tid; t < 2048; t += 256) s += expf(g_logits[(size_t)t * 128 + o] - m);
    red[tid] = s; __syncthreads();
    for (int st = 128; st > 0; st >>= 1) {
        if (tid < st) red[tid] += red[tid + st];
        __syncthreads();
    }
    float lse = m + logf(red[0]);
    for (int t = tid; t < 2048; t += 256)
        out[(size_t)t * 128 + o] = g_logits[(size_t)t * 128 + o] - lse;
}

// ---------------- host ----------------
static inline int ntiles(int M, int N) { return ((M + 127) / 128) * (N / 64); }

extern "C" void kernel_launch(void* const* d_in, const int* in_sizes, int n_in,
                              void* d_out, int out_size)
{
    const float* tree_features = (const float*)d_in[0];
    const float* features      = (const float*)d_in[1];
    const float* W_iou = (const float*)d_in[2];
    const float* b_iou = (const float*)d_in[3];
    const float* U_iou = (const float*)d_in[4];
    const float* W_f   = (const float*)d_in[5];
    const float* b_f   = (const float*)d_in[6];
    const float* U_f   = (const float*)d_in[7];
    const float* W_ih  = (const float*)d_in[8];
    const float* b_ih  = (const float*)d_in[9];
    const float* W_hh  = (const float*)d_in[10];
    const float* b_hh  = (const float*)d_in[11];
    const float* W_cls = (const float*)d_in[12];
    const float* b_cls = (const float*)d_in[13];
    float* out = (float*)d_out;

    float *xiou, *xf, *xih, *h, *iou, *fh, *cls, *logits;
    cudaGetSymbolAddress((void**)&xiou,   g_xiou);
    cudaGetSymbolAddress((void**)&xf,     g_xf);
    cudaGetSymbolAddress((void**)&xih,    g_xih);
    cudaGetSymbolAddress((void**)&h,      g_h);
    cudaGetSymbolAddress((void**)&iou,    g_iou);
    cudaGetSymbolAddress((void**)&fh,     g_fh);
    cudaGetSymbolAddress((void**)&cls,    g_cls);
    cudaGetSymbolAddress((void**)&logits, g_logits);

    static cudaStream_t s2 = nullptr;
    static cudaEvent_t evFork = nullptr, evJoin = nullptr;
    if (!s2) {
        cudaStreamCreateWithFlags(&s2, cudaStreamNonBlocking);
        cudaEventCreateWithFlags(&evFork, cudaEventDisableTiming);
        cudaEventCreateWithFlags(&evJoin, cudaEventDisableTiming);
    }

    // ---- reset ring + residency counter + full xih GEMM (stream 0) ----
    zero_misc<<<3, 256>>>();
    GemmP pih = { features, W_ih, b_ih, b_hh, xih, 2048, 3072, 768, 768, 768, -1, 0 };
    gemm_single<<<ntiles(2048, 3072), 256>>>(pih);

    // ---- fork: seq LSTM on its own stream ----
    cudaEventRecord(evFork, 0);
    cudaStreamWaitEvent(s2, evFork, 0);
    lstm_seq<<<96, 256, 0, s2>>>(W_hh);
    cudaEventRecord(evJoin, s2);

    // ---- gate stream 0 until all 96 LSTM CTAs are resident ----
    wait_resident<<<1, 32>>>(96u);

    // ---- tree branch (stream 0, overlapped with LSTM) ----
    GemmP piou = { tree_features, W_iou, b_iou, nullptr, xiou, 2048, 2304, 768, 768, 768, -1, 0 };
    gemm_single<<<ntiles(2048, 2304), 256>>>(piou);
    // x_f only needed for parent nodes 0..1023 (leaves have no children)
    GemmP pxf = { tree_features, W_f, b_f, nullptr, xf, 1024, 768, 768, 768, 768, -1, 0 };
    gemm_single<<<ntiles(1024, 768), 256>>>(pxf);

    leaf_combine<<<(1024 * 768) / 256, 256>>>();
    for (int lvl = 1; lvl <= 11; lvl++) {
        int s, cnt, cs, e;
        if (lvl <= 10) {
            s = 1 << (10 - lvl);
            cnt = s;
            cs = 2 * s + 1;
            int last = 4 * s; if (last > 2047) last = 2047;
            e = last - 2 * s;
        } else {
            s = 0; cnt = 1; cs = 1; e = 2;
        }
        GemmP p1 = { nullptr, U_iou, nullptr, nullptr, iou, cnt, 2304, 768, 768, 768, s, 0 };
        GemmP p2 = { h + (size_t)cs * 768, U_f, nullptr, nullptr, fh, e, 768, 768, 768, 768, -1, 0 };
        int t1 = ntiles(cnt, 2304), t2 = ntiles(e, 768);
        gemm_dual<<<t1 + t2, 256>>>(p1, p2, t1);
        node_combine<<<(cnt * 768 + 255) / 256, 256>>>(s, cnt, cs);
    }

    // ---- classifier tree-half (hidden under LSTM) ----
    GemmP pcls1 = { cls, W_cls, b_cls, nullptr, logits, 2048, 128, 768, 1536, 1536, -1, 0 };
    gemm_single<<<ntiles(2048, 128), 256>>>(pcls1);

    // ---- join + classifier lstm-half (accumulating) + log_softmax over axis 0
    cudaStreamWaitEvent(0, evJoin, 0);
    GemmP pcls2 = { cls + 768, W_cls + 768, nullptr, nullptr, logits, 2048, 128, 768, 1536, 1536, -1, 1 };
    gemm_single<<<ntiles(2048, 128), 256>>>(pcls2);
    logsoftmax_col<<<128, 256>>>(out);
}